// round 7
// baseline (speedup 1.0000x reference)
#include <cuda_runtime.h>
#include <math.h>

// ---------------------------------------------------------------------------
// Problem constants
// ---------------------------------------------------------------------------
#define NN     50000
#define MUL0   16
#define MUL1   8
#define RBF    8
#define HID    64
#define WNUM   576          // 256 + 128 + 128 + 64
#define CUTOFF 5.0f

#define A_PATH     0.20412414523193150818f   // 1/sqrt(24)
#define INV_SQRT3  0.57735026918962576451f
#define INV_SQRT8  0.35355339059327376220f
#define PI_OVER_C  0.62831853071795864769f   // pi / 5

// Device-global scratch (allocation-free)
__device__ float g_xnorm[NN * 40];
__device__ float g_agg[NN * 41];   // [0,N*16): agg0 | [N*16,N*40): agg1 | [N*40,N*41): norm

__device__ __forceinline__ float sigf(float x) {
    return __fdividef(1.0f, 1.0f + __expf(-x));
}

// ---------------------------------------------------------------------------
// Kernel 1: irrep norm + zero aggregation buffers
// ---------------------------------------------------------------------------
__global__ void k_norm(const float* __restrict__ x, int nN)
{
    int n = blockIdx.x * blockDim.x + threadIdx.x;
    if (n >= nN) return;
    const float* xi = x + (size_t)n * 40;
    float b[40];
#pragma unroll
    for (int i = 0; i < 40; i++) b[i] = xi[i];
    float ss = 0.f, vs = 0.f;
#pragma unroll
    for (int i = 0; i < 16; i++) ss = fmaf(b[i], b[i], ss);
#pragma unroll
    for (int i = 16; i < 40; i++) vs = fmaf(b[i], b[i], vs);
    float inv_s = rsqrtf(ss * 0.0625f + 1e-8f);   // mean over 16 scalars
    float inv_v = rsqrtf(vs * 0.125f  + 1e-8f);   // mean over 8 vector norms
    float* xo = g_xnorm + (size_t)n * 40;
#pragma unroll
    for (int i = 0; i < 16; i++) xo[i] = b[i] * inv_s;
#pragma unroll
    for (int i = 16; i < 40; i++) xo[i] = b[i] * inv_v;

    float* a0 = g_agg + (size_t)n * 16;
#pragma unroll
    for (int i = 0; i < 16; i++) a0[i] = 0.f;
    float* a1 = g_agg + (size_t)nN * 16 + (size_t)n * 24;
#pragma unroll
    for (int i = 0; i < 24; i++) a1[i] = 0.f;
    g_agg[(size_t)nN * 40 + n] = 0.f;
}

// ---------------------------------------------------------------------------
// Kernel 2: fused edge kernel. One thread per edge; all weight reads are
// warp-broadcast LDS from shared memory (W_r2 staged: 144 KB).
// ---------------------------------------------------------------------------
__global__ void __launch_bounds__(256, 1)
k_edge(const int*   __restrict__ esrc,  const int*   __restrict__ edst,
       const float* __restrict__ esh,   const float* __restrict__ erbf,
       const float* __restrict__ elen,
       const float* __restrict__ wr1,   const float* __restrict__ br1,
       const float* __restrict__ wr2,   const float* __restrict__ br2,
       const float* __restrict__ wg1,   const float* __restrict__ bg1,
       const float* __restrict__ wg2,   const float* __restrict__ bg2,
       int E, int nN)
{
    extern __shared__ float sm[];
    float* sWr2 = sm;              // 36864
    float* sWr1 = sWr2 + 36864;    // 512
    float* sWg1 = sWr1 + 512;      // 512
    float* sWg2 = sWg1 + 512;      // 64
    float* sBr1 = sWg2 + 64;       // 64
    float* sBg1 = sBr1 + 64;       // 64
    float* sBr2 = sBg1 + 64;       // 576
    // total 38656 floats = 154624 bytes

    for (int i = threadIdx.x; i < 36864 / 4; i += blockDim.x)
        ((float4*)sWr2)[i] = ((const float4*)wr2)[i];
    for (int i = threadIdx.x; i < 512; i += blockDim.x) { sWr1[i] = wr1[i]; sWg1[i] = wg1[i]; }
    for (int i = threadIdx.x; i < 64;  i += blockDim.x) { sWg2[i] = wg2[i]; sBr1[i] = br1[i]; sBg1[i] = bg1[i]; }
    for (int i = threadIdx.x; i < 576; i += blockDim.x) sBr2[i] = br2[i];
    __syncthreads();

    int e = blockIdx.x * blockDim.x + threadIdx.x;
    if (e >= E) return;

    int src = esrc[e];
    int dst = edst[e];
    float4 sh = ((const float4*)esh)[e];
    const float sh0 = sh.x, s1x = sh.y, s1y = sh.z, s1z = sh.w;
    float len = elen[e];

    float rb[8];
    {
        const float4* rp = (const float4*)(erbf + (size_t)e * 8);
        float4 r0 = rp[0], r1 = rp[1];
        rb[0] = r0.x; rb[1] = r0.y; rb[2] = r0.z; rb[3] = r0.w;
        rb[4] = r1.x; rb[5] = r1.y; rb[6] = r1.z; rb[7] = r1.w;
    }

    // ---- hidden layers of both MLPs (vectorized LDS.128, static reg indices)
    float H[64], G[64];
#pragma unroll
    for (int h = 0; h < 64; h++) { H[h] = sBr1[h]; G[h] = sBg1[h]; }
#pragma unroll
    for (int r = 0; r < 8; r++) {
        float rv = rb[r];
        const float4* wrp = (const float4*)(sWr1 + r * 64);
        const float4* wgp = (const float4*)(sWg1 + r * 64);
#pragma unroll
        for (int h4 = 0; h4 < 16; h4++) {
            float4 wa = wrp[h4], wb = wgp[h4];
            H[4*h4+0] = fmaf(rv, wa.x, H[4*h4+0]);
            H[4*h4+1] = fmaf(rv, wa.y, H[4*h4+1]);
            H[4*h4+2] = fmaf(rv, wa.z, H[4*h4+2]);
            H[4*h4+3] = fmaf(rv, wa.w, H[4*h4+3]);
            G[4*h4+0] = fmaf(rv, wb.x, G[4*h4+0]);
            G[4*h4+1] = fmaf(rv, wb.y, G[4*h4+1]);
            G[4*h4+2] = fmaf(rv, wb.z, G[4*h4+2]);
            G[4*h4+3] = fmaf(rv, wb.w, G[4*h4+3]);
        }
    }
    float z = 0.f;
#pragma unroll
    for (int h = 0; h < 64; h++) {
        float hr = H[h]; H[h] = hr * sigf(hr);           // silu
        float hg = G[h]; z = fmaf(hg * sigf(hg), sWg2[h], z);
    }
    float gw = sigf(z + bg2[0]);
    float cw = (len < CUTOFF) ? 0.5f * (cosf(PI_OVER_C * len) + 1.0f) : 0.0f;
    float ew = cw * gw;

    // ---- gather source node features into a local array (dynamic-index OK)
    float xe[40];
    {
        const float4* xr = (const float4*)(g_xnorm + (size_t)src * 40);
#pragma unroll
        for (int q = 0; q < 10; q++) ((float4*)xe)[q] = xr[q];
    }

    float m0[16], m1[24];
#pragma unroll
    for (int j = 0; j < 16; j++) m0[j] = 0.f;
#pragma unroll
    for (int j = 0; j < 24; j++) m1[j] = 0.f;

    // ---- region 1: w1[i][j], k = i*16 + j, coef a_i = s_i * sh0 -> m0[j]
#pragma unroll 1
    for (int i = 0; i < 16; i++) {
        float a = xe[i] * sh0;
        const float* Wk = sWr2 + i * 16;
        const float* Bk = sBr2 + i * 16;
        float acc[16];
#pragma unroll
        for (int j = 0; j < 16; j++) acc[j] = Bk[j];
#pragma unroll
        for (int h = 0; h < 64; h++) {
            const float4* wp = (const float4*)(Wk + h * 576);
            float hv = H[h];
#pragma unroll
            for (int q = 0; q < 4; q++) {
                float4 w = wp[q];
                acc[4*q+0] = fmaf(hv, w.x, acc[4*q+0]);
                acc[4*q+1] = fmaf(hv, w.y, acc[4*q+1]);
                acc[4*q+2] = fmaf(hv, w.z, acc[4*q+2]);
                acc[4*q+3] = fmaf(hv, w.w, acc[4*q+3]);
            }
        }
#pragma unroll
        for (int j = 0; j < 16; j++) m0[j] = fmaf(a, acc[j], m0[j]);
    }

    // ---- region 2: w2[i][j], k = 256 + i*16 + j, coef b_i = inv_sqrt3*(v_i . sh1)
#pragma unroll 1
    for (int i = 0; i < 8; i++) {
        float b = INV_SQRT3 * (xe[16 + 3*i] * s1x + xe[17 + 3*i] * s1y + xe[18 + 3*i] * s1z);
        const float* Wk = sWr2 + 256 + i * 16;
        const float* Bk = sBr2 + 256 + i * 16;
        float acc[16];
#pragma unroll
        for (int j = 0; j < 16; j++) acc[j] = Bk[j];
#pragma unroll
        for (int h = 0; h < 64; h++) {
            const float4* wp = (const float4*)(Wk + h * 576);
            float hv = H[h];
#pragma unroll
            for (int q = 0; q < 4; q++) {
                float4 w = wp[q];
                acc[4*q+0] = fmaf(hv, w.x, acc[4*q+0]);
                acc[4*q+1] = fmaf(hv, w.y, acc[4*q+1]);
                acc[4*q+2] = fmaf(hv, w.z, acc[4*q+2]);
                acc[4*q+3] = fmaf(hv, w.w, acc[4*q+3]);
            }
        }
#pragma unroll
        for (int j = 0; j < 16; j++) m0[j] = fmaf(b, acc[j], m0[j]);
    }

    // ---- region 3: w3[i][j], k = 384 + i*8 + j, m1[j][c] += s_i * w3 * sh1[c]
#pragma unroll 1
    for (int i = 0; i < 16; i++) {
        float s = xe[i];
        const float* Wk = sWr2 + 384 + i * 8;
        const float* Bk = sBr2 + 384 + i * 8;
        float acc[8];
#pragma unroll
        for (int j = 0; j < 8; j++) acc[j] = Bk[j];
#pragma unroll
        for (int h = 0; h < 64; h++) {
            const float4* wp = (const float4*)(Wk + h * 576);
            float hv = H[h];
#pragma unroll
            for (int q = 0; q < 2; q++) {
                float4 w = wp[q];
                acc[4*q+0] = fmaf(hv, w.x, acc[4*q+0]);
                acc[4*q+1] = fmaf(hv, w.y, acc[4*q+1]);
                acc[4*q+2] = fmaf(hv, w.z, acc[4*q+2]);
                acc[4*q+3] = fmaf(hv, w.w, acc[4*q+3]);
            }
        }
#pragma unroll
        for (int j = 0; j < 8; j++) {
            float t = s * acc[j];
            m1[3*j+0] = fmaf(t, s1x, m1[3*j+0]);
            m1[3*j+1] = fmaf(t, s1y, m1[3*j+1]);
            m1[3*j+2] = fmaf(t, s1z, m1[3*j+2]);
        }
    }

    // ---- region 4: w4[i][j], k = 512 + i*8 + j, m1[j][c] += v[i][c]*sh0 * w4
#pragma unroll 1
    for (int i = 0; i < 8; i++) {
        float vx = xe[16 + 3*i] * sh0;
        float vy = xe[17 + 3*i] * sh0;
        float vz = xe[18 + 3*i] * sh0;
        const float* Wk = sWr2 + 512 + i * 8;
        const float* Bk = sBr2 + 512 + i * 8;
        float acc[8];
#pragma unroll
        for (int j = 0; j < 8; j++) acc[j] = Bk[j];
#pragma unroll
        for (int h = 0; h < 64; h++) {
            const float4* wp = (const float4*)(Wk + h * 576);
            float hv = H[h];
#pragma unroll
            for (int q = 0; q < 2; q++) {
                float4 w = wp[q];
                acc[4*q+0] = fmaf(hv, w.x, acc[4*q+0]);
                acc[4*q+1] = fmaf(hv, w.y, acc[4*q+1]);
                acc[4*q+2] = fmaf(hv, w.z, acc[4*q+2]);
                acc[4*q+3] = fmaf(hv, w.w, acc[4*q+3]);
            }
        }
#pragma unroll
        for (int j = 0; j < 8; j++) {
            m1[3*j+0] = fmaf(vx, acc[j], m1[3*j+0]);
            m1[3*j+1] = fmaf(vy, acc[j], m1[3*j+1]);
            m1[3*j+2] = fmaf(vz, acc[j], m1[3*j+2]);
        }
    }

    // ---- scale + scatter
    float c0 = A_PATH * ew;
    float* a0 = g_agg + (size_t)dst * 16;
#pragma unroll
    for (int j = 0; j < 16; j++) atomicAdd(a0 + j, c0 * m0[j]);
    float* a1 = g_agg + (size_t)nN * 16 + (size_t)dst * 24;
#pragma unroll
    for (int j = 0; j < 24; j++) atomicAdd(a1 + j, c0 * m1[j]);
    atomicAdd(g_agg + (size_t)nN * 40 + dst, ew);
}

// ---------------------------------------------------------------------------
// Kernel 3: node update (gates + small matmuls + residual)
// ---------------------------------------------------------------------------
__global__ void k_node(const float* __restrict__ x,
                       const float* __restrict__ Wms, const float* __restrict__ Wmv,
                       const float* __restrict__ Wus, const float* __restrict__ Wuv,
                       const float* __restrict__ Wss, const float* __restrict__ Wsv,
                       const float* __restrict__ rsp,
                       float* __restrict__ out, int nN)
{
    __shared__ float sWms[384], sWmv[64], sWus[256], sWuv[64], sWss[256], sWsv[64];
    int t = threadIdx.x;
    for (int i = t; i < 384; i += blockDim.x) sWms[i] = Wms[i];
    for (int i = t; i < 256; i += blockDim.x) { sWus[i] = Wus[i]; sWss[i] = Wss[i]; }
    for (int i = t; i < 64;  i += blockDim.x) { sWmv[i] = Wmv[i]; sWuv[i] = Wuv[i]; sWsv[i] = Wsv[i]; }
    __syncthreads();

    int n = blockIdx.x * blockDim.x + t;
    if (n >= nN) return;

    float rs = rsp[0];
    float nrm = fmaxf(g_agg[(size_t)nN * 40 + n], 1e-8f);
    float inv = __fdividef(1.0f, nrm);

    float a0[16], a1[24];
#pragma unroll
    for (int j = 0; j < 16; j++) a0[j] = g_agg[(size_t)n * 16 + j] * inv;
#pragma unroll
    for (int j = 0; j < 24; j++) a1[j] = g_agg[(size_t)nN * 16 + (size_t)n * 24 + j] * inv;

    // sc = agg0 @ Wm_s / 4
    float sc[24];
#pragma unroll
    for (int j = 0; j < 24; j++) sc[j] = 0.f;
#pragma unroll
    for (int i = 0; i < 16; i++) {
        float ai = a0[i];
#pragma unroll
        for (int j = 0; j < 24; j++) sc[j] = fmaf(ai, sWms[i * 24 + j], sc[j]);
    }

    float scal[16], gate[8];
#pragma unroll
    for (int j = 0; j < 16; j++) { float v = 0.25f * sc[j]; scal[j] = v * sigf(v); }
#pragma unroll
    for (int j = 0; j < 8;  j++) gate[j] = sigf(0.25f * sc[16 + j]);

    // vg[j][c] = gate[j] * (sum_i a1[i][c] * Wm_v[i][j]) / sqrt(8)
    float vg[24];
#pragma unroll
    for (int j = 0; j < 8; j++) {
#pragma unroll
        for (int c = 0; c < 3; c++) {
            float acc = 0.f;
#pragma unroll
            for (int i = 0; i < 8; i++) acc = fmaf(a1[i * 3 + c], sWmv[i * 8 + j], acc);
            vg[3 * j + c] = acc * INV_SQRT8 * gate[j];
        }
    }

    const float* xn = g_xnorm + (size_t)n * 40;
    float xs[16], xv[24];
#pragma unroll
    for (int i = 0; i < 16; i++) xs[i] = xn[i];
#pragma unroll
    for (int i = 0; i < 24; i++) xv[i] = xn[16 + i];

    const float* xi = x + (size_t)n * 40;
    float* o = out + (size_t)n * 40;

#pragma unroll
    for (int j = 0; j < 16; j++) {
        float acc = 0.f;
#pragma unroll
        for (int i = 0; i < 16; i++) {
            acc = fmaf(scal[i], sWus[i * 16 + j], acc);
            acc = fmaf(xs[i],  sWss[i * 16 + j], acc);
        }
        o[j] = xi[j] + rs * 0.25f * acc;
    }
#pragma unroll
    for (int j = 0; j < 8; j++) {
#pragma unroll
        for (int c = 0; c < 3; c++) {
            float acc = 0.f;
#pragma unroll
            for (int i = 0; i < 8; i++) {
                acc = fmaf(vg[3 * i + c], sWuv[i * 8 + j], acc);
                acc = fmaf(xv[3 * i + c], sWsv[i * 8 + j], acc);
            }
            o[16 + 3 * j + c] = xi[16 + 3 * j + c] + rs * INV_SQRT8 * acc;
        }
    }
}

// ---------------------------------------------------------------------------
// Launch
// ---------------------------------------------------------------------------
extern "C" void kernel_launch(void* const* d_in, const int* in_sizes, int n_in,
                              void* d_out, int out_size)
{
    const float* x    = (const float*)d_in[0];
    const int*   esrc = (const int*)  d_in[1];
    const int*   edst = (const int*)  d_in[2];
    const float* esh  = (const float*)d_in[3];
    const float* erbf = (const float*)d_in[4];
    const float* elen = (const float*)d_in[5];
    const float* wr1  = (const float*)d_in[6];
    const float* br1  = (const float*)d_in[7];
    const float* wr2  = (const float*)d_in[8];
    const float* br2  = (const float*)d_in[9];
    const float* wg1  = (const float*)d_in[10];
    const float* bg1  = (const float*)d_in[11];
    const float* wg2  = (const float*)d_in[12];
    const float* bg2  = (const float*)d_in[13];
    const float* Wms  = (const float*)d_in[14];
    const float* Wmv  = (const float*)d_in[15];
    const float* Wus  = (const float*)d_in[16];
    const float* Wuv  = (const float*)d_in[17];
    const float* Wss  = (const float*)d_in[18];
    const float* Wsv  = (const float*)d_in[19];
    const float* rsp  = (const float*)d_in[20];

    int nN = in_sizes[0] / 40;
    int E  = in_sizes[1];
    float* out = (float*)d_out;

    size_t shbytes = 38656 * sizeof(float);   // 154624 B
    cudaFuncSetAttribute(k_edge, cudaFuncAttributeMaxDynamicSharedMemorySize, (int)shbytes);

    k_norm<<<(nN + 255) / 256, 256>>>(x, nN);
    k_edge<<<(E + 255) / 256, 256, shbytes>>>(esrc, edst, esh, erbf, elen,
                                              wr1, br1, wr2, br2,
                                              wg1, bg1, wg2, bg2, E, nN);
    k_node<<<(nN + 255) / 256, 256>>>(x, Wms, Wmv, Wus, Wuv, Wss, Wsv, rsp, out, nN);
}

// round 8
// speedup vs baseline: 1.0726x; 1.0726x over previous
#include <cuda_runtime.h>
#include <math.h>

// ---------------------------------------------------------------------------
// Problem constants
// ---------------------------------------------------------------------------
#define CUTOFF     5.0f
#define A_PATH     0.20412414523193150818f   // 1/sqrt(24)
#define INV_SQRT3  0.57735026918962576451f
#define INV_SQRT8  0.35355339059327376220f
#define PI_OVER_C  0.62831853071795864769f   // pi / 5

#define NNMAX 50000
__device__ float g_xnorm[NNMAX * 40];
__device__ float g_agg[NNMAX * 41];   // [0,N*16): agg0 | [N*16,N*40): agg1 | [N*40,N*41): norm

typedef unsigned long long u64;

__device__ __forceinline__ float sigf(float x) {
    return __fdividef(1.0f, 1.0f + __expf(-x));
}
// duplicate a float into both halves of an f32x2 operand
__device__ __forceinline__ u64 pk2(float x) {
    u64 r; unsigned u = __float_as_uint(x);
    asm("mov.b64 %0, {%1, %1};" : "=l"(r) : "r"(u));
    return r;
}
// d = a * b + d   (two independent fp32 FMAs, Blackwell packed pipe)
__device__ __forceinline__ void fma2(u64& d, u64 a, u64 b) {
    asm("fma.rn.f32x2 %0, %1, %2, %0;" : "+l"(d) : "l"(a), "l"(b));
}
__device__ __forceinline__ float lo2(u64 v) { return __uint_as_float((unsigned)v); }
__device__ __forceinline__ float hi2(u64 v) { return __uint_as_float((unsigned)(v >> 32)); }

// ---------------------------------------------------------------------------
// Kernel 0: zero aggregation scratch (coalesced)
// ---------------------------------------------------------------------------
__global__ void k_zero(int total)   // total = nN*41 floats
{
    int i = blockIdx.x * blockDim.x + threadIdx.x;
    int nf4 = total >> 2;
    float4 z = make_float4(0.f, 0.f, 0.f, 0.f);
    if (i < nf4) ((float4*)g_agg)[i] = z;
    if (i < (total & 3)) g_agg[(nf4 << 2) + i] = 0.f;
}

// ---------------------------------------------------------------------------
// Kernel 1: irrep norm (smem-staged, coalesced)
// ---------------------------------------------------------------------------
__global__ void __launch_bounds__(256)
k_norm(const float* __restrict__ x, int nN)
{
    __shared__ float sx[256 * 40];
    int base = blockIdx.x * 256;
    int nNodes = nN - base; if (nNodes > 256) nNodes = 256;
    int nf4 = nNodes * 10;

    const float4* xin = (const float4*)(x + (size_t)base * 40);
    for (int i = threadIdx.x; i < nf4; i += 256) ((float4*)sx)[i] = xin[i];
    __syncthreads();

    int t = threadIdx.x;
    if (t < nNodes) {
        float* b = sx + t * 40;
        float ss = 0.f, vs = 0.f;
#pragma unroll
        for (int i = 0; i < 16; i++) ss = fmaf(b[i], b[i], ss);
#pragma unroll
        for (int i = 16; i < 40; i++) vs = fmaf(b[i], b[i], vs);
        float inv_s = rsqrtf(ss * 0.0625f + 1e-8f);
        float inv_v = rsqrtf(vs * 0.125f  + 1e-8f);
#pragma unroll
        for (int i = 0; i < 16; i++) b[i] *= inv_s;
#pragma unroll
        for (int i = 16; i < 40; i++) b[i] *= inv_v;
    }
    __syncthreads();
    float4* xout = (float4*)(g_xnorm + (size_t)base * 40);
    for (int i = threadIdx.x; i < nf4; i += 256) xout[i] = ((float4*)sx)[i];
}

// ---------------------------------------------------------------------------
// Kernel 2: fused edge kernel. One thread per edge; packed f32x2 FMA on
// column pairs; all weight reads are warp-broadcast LDS.128 from smem.
// ---------------------------------------------------------------------------
__global__ void __launch_bounds__(256, 1)
k_edge(const int*   __restrict__ esrc,  const int*   __restrict__ edst,
       const float* __restrict__ esh,   const float* __restrict__ erbf,
       const float* __restrict__ elen,
       const float* __restrict__ wr1,   const float* __restrict__ br1,
       const float* __restrict__ wr2,   const float* __restrict__ br2,
       const float* __restrict__ wg1,   const float* __restrict__ bg1,
       const float* __restrict__ wg2,   const float* __restrict__ bg2,
       int E, int nN)
{
    extern __shared__ float sm[];
    float* sWr2 = sm;              // 36864
    float* sWr1 = sWr2 + 36864;    // 512
    float* sWg1 = sWr1 + 512;      // 512
    float* sWg2 = sWg1 + 512;      // 64
    float* sBr1 = sWg2 + 64;       // 64
    float* sBg1 = sBr1 + 64;       // 64
    float* sBr2 = sBg1 + 64;       // 576
    // total 38656 floats = 154624 bytes

    for (int i = threadIdx.x; i < 36864 / 4; i += blockDim.x)
        ((float4*)sWr2)[i] = ((const float4*)wr2)[i];
    for (int i = threadIdx.x; i < 512; i += blockDim.x) { sWr1[i] = wr1[i]; sWg1[i] = wg1[i]; }
    for (int i = threadIdx.x; i < 64;  i += blockDim.x) { sWg2[i] = wg2[i]; sBr1[i] = br1[i]; sBg1[i] = bg1[i]; }
    for (int i = threadIdx.x; i < 576; i += blockDim.x) sBr2[i] = br2[i];
    __syncthreads();

    int e = blockIdx.x * blockDim.x + threadIdx.x;
    if (e >= E) return;

    int src = esrc[e];
    int dst = edst[e];
    float4 sh = ((const float4*)esh)[e];
    const float sh0 = sh.x, s1x = sh.y, s1y = sh.z, s1z = sh.w;
    float len = elen[e];

    float rb[8];
    {
        const float4* rp = (const float4*)(erbf + (size_t)e * 8);
        float4 r0 = rp[0], r1 = rp[1];
        rb[0] = r0.x; rb[1] = r0.y; rb[2] = r0.z; rb[3] = r0.w;
        rb[4] = r1.x; rb[5] = r1.y; rb[6] = r1.z; rb[7] = r1.w;
    }

    // ---- hidden layers of both MLPs: packed f32x2 pairs over hidden units
    u64 Hp[32], Gp[32];
    {
        const ulonglong2* bh = (const ulonglong2*)sBr1;
        const ulonglong2* bg = (const ulonglong2*)sBg1;
#pragma unroll
        for (int q = 0; q < 16; q++) {
            ulonglong2 th = bh[q], tg = bg[q];
            Hp[2*q] = th.x; Hp[2*q+1] = th.y;
            Gp[2*q] = tg.x; Gp[2*q+1] = tg.y;
        }
#pragma unroll 1
        for (int r = 0; r < 8; r++) {
            u64 rv2 = pk2(rb[r]);
            const ulonglong2* wr = (const ulonglong2*)(sWr1 + r * 64);
            const ulonglong2* wg = (const ulonglong2*)(sWg1 + r * 64);
#pragma unroll
            for (int q = 0; q < 16; q++) {
                ulonglong2 a = wr[q], b = wg[q];
                fma2(Hp[2*q],   rv2, a.x);
                fma2(Hp[2*q+1], rv2, a.y);
                fma2(Gp[2*q],   rv2, b.x);
                fma2(Gp[2*q+1], rv2, b.y);
            }
        }
    }
    float H[64];
    float z = 0.f;
#pragma unroll
    for (int q = 0; q < 32; q++) {
        float h0 = lo2(Hp[q]), h1 = hi2(Hp[q]);
        H[2*q]   = h0 * sigf(h0);
        H[2*q+1] = h1 * sigf(h1);
        float g0 = lo2(Gp[q]), g1 = hi2(Gp[q]);
        z = fmaf(g0 * sigf(g0), sWg2[2*q],   z);
        z = fmaf(g1 * sigf(g1), sWg2[2*q+1], z);
    }
    float gw = sigf(z + bg2[0]);
    float cw = (len < CUTOFF) ? 0.5f * (cosf(PI_OVER_C * len) + 1.0f) : 0.0f;
    float ew = cw * gw;

    // ---- gather source node features
    float xe[40];
    {
        const float4* xr = (const float4*)(g_xnorm + (size_t)src * 40);
#pragma unroll
        for (int q = 0; q < 10; q++) ((float4*)xe)[q] = xr[q];
    }

    // ---- coefficient tables for the two merged region loops
    // m0 loop (cols i*16, i in 0..23):  i<16: a_i = s_i*sh0 ; i>=16: b = 1/sqrt3 * (v . sh1)
    float cA[24];
#pragma unroll
    for (int i = 0; i < 16; i++) cA[i] = xe[i] * sh0;
#pragma unroll
    for (int i = 0; i < 8; i++)
        cA[16 + i] = INV_SQRT3 * (xe[16 + 3*i] * s1x + xe[17 + 3*i] * s1y + xe[18 + 3*i] * s1z);
    // m1 loop (cols 384 + i*8, i in 0..23):  i<16: P = s_i*sh1 ; i>=16: P = v[i-16]*sh0
    float P[24][3];
#pragma unroll
    for (int i = 0; i < 16; i++) { P[i][0] = xe[i] * s1x; P[i][1] = xe[i] * s1y; P[i][2] = xe[i] * s1z; }
#pragma unroll
    for (int i = 0; i < 8; i++) {
        P[16+i][0] = xe[16 + 3*i] * sh0;
        P[16+i][1] = xe[17 + 3*i] * sh0;
        P[16+i][2] = xe[18 + 3*i] * sh0;
    }

    // ---- m0: regions 1+2 merged, packed column pairs
    u64 m0p[8];
#pragma unroll
    for (int q = 0; q < 8; q++) m0p[q] = 0ull;

#pragma unroll 1
    for (int i = 0; i < 24; i++) {
        u64 c2 = pk2(cA[i]);
        const float* colbase = sWr2 + i * 16;
        u64 acc[8];
        {
            const ulonglong2* bp = (const ulonglong2*)(sBr2 + i * 16);
            ulonglong2 b0 = bp[0], b1 = bp[1], b2 = bp[2], b3 = bp[3];
            acc[0] = b0.x; acc[1] = b0.y; acc[2] = b1.x; acc[3] = b1.y;
            acc[4] = b2.x; acc[5] = b2.y; acc[6] = b3.x; acc[7] = b3.y;
        }
#pragma unroll
        for (int h = 0; h < 64; h++) {
            u64 h2 = pk2(H[h]);
            const ulonglong2* wp = (const ulonglong2*)(colbase + h * 576);
            ulonglong2 w0 = wp[0], w1 = wp[1], w2 = wp[2], w3 = wp[3];
            fma2(acc[0], h2, w0.x); fma2(acc[1], h2, w0.y);
            fma2(acc[2], h2, w1.x); fma2(acc[3], h2, w1.y);
            fma2(acc[4], h2, w2.x); fma2(acc[5], h2, w2.y);
            fma2(acc[6], h2, w3.x); fma2(acc[7], h2, w3.y);
        }
#pragma unroll
        for (int q = 0; q < 8; q++) fma2(m0p[q], c2, acc[q]);
    }

    // ---- m1: regions 3+4 merged, packed column pairs
    float m1v[24];
#pragma unroll
    for (int j = 0; j < 24; j++) m1v[j] = 0.f;

#pragma unroll 1
    for (int i = 0; i < 24; i++) {
        const float* colbase = sWr2 + 384 + i * 8;
        u64 acc[4];
        {
            const ulonglong2* bp = (const ulonglong2*)(sBr2 + 384 + i * 8);
            ulonglong2 b0 = bp[0], b1 = bp[1];
            acc[0] = b0.x; acc[1] = b0.y; acc[2] = b1.x; acc[3] = b1.y;
        }
#pragma unroll
        for (int h = 0; h < 64; h++) {
            u64 h2 = pk2(H[h]);
            const ulonglong2* wp = (const ulonglong2*)(colbase + h * 576);
            ulonglong2 w0 = wp[0], w1 = wp[1];
            fma2(acc[0], h2, w0.x); fma2(acc[1], h2, w0.y);
            fma2(acc[2], h2, w1.x); fma2(acc[3], h2, w1.y);
        }
        float px = P[i][0], py = P[i][1], pz = P[i][2];
#pragma unroll
        for (int q = 0; q < 4; q++) {
            float a0 = lo2(acc[q]), a1 = hi2(acc[q]);
            int j0 = 2*q, j1 = 2*q + 1;
            m1v[3*j0+0] = fmaf(px, a0, m1v[3*j0+0]);
            m1v[3*j0+1] = fmaf(py, a0, m1v[3*j0+1]);
            m1v[3*j0+2] = fmaf(pz, a0, m1v[3*j0+2]);
            m1v[3*j1+0] = fmaf(px, a1, m1v[3*j1+0]);
            m1v[3*j1+1] = fmaf(py, a1, m1v[3*j1+1]);
            m1v[3*j1+2] = fmaf(pz, a1, m1v[3*j1+2]);
        }
    }

    // ---- scale + scatter
    float c0 = A_PATH * ew;
    float* a0 = g_agg + (size_t)dst * 16;
#pragma unroll
    for (int q = 0; q < 8; q++) {
        atomicAdd(a0 + 2*q,     c0 * lo2(m0p[q]));
        atomicAdd(a0 + 2*q + 1, c0 * hi2(m0p[q]));
    }
    float* a1 = g_agg + (size_t)nN * 16 + (size_t)dst * 24;
#pragma unroll
    for (int j = 0; j < 24; j++) atomicAdd(a1 + j, c0 * m1v[j]);
    atomicAdd(g_agg + (size_t)nN * 40 + dst, ew);
}

// ---------------------------------------------------------------------------
// Kernel 3: node update (gates + small matmuls + residual)
// ---------------------------------------------------------------------------
__global__ void __launch_bounds__(256)
k_node(const float* __restrict__ x,
       const float* __restrict__ Wms, const float* __restrict__ Wmv,
       const float* __restrict__ Wus, const float* __restrict__ Wuv,
       const float* __restrict__ Wss, const float* __restrict__ Wsv,
       const float* __restrict__ rsp,
       float* __restrict__ out, int nN)
{
    __shared__ float sWms[384], sWmv[64], sWus[256], sWuv[64], sWss[256], sWsv[64];
    int t = threadIdx.x;
    for (int i = t; i < 384; i += blockDim.x) sWms[i] = Wms[i];
    for (int i = t; i < 256; i += blockDim.x) { sWus[i] = Wus[i]; sWss[i] = Wss[i]; }
    for (int i = t; i < 64;  i += blockDim.x) { sWmv[i] = Wmv[i]; sWuv[i] = Wuv[i]; sWsv[i] = Wsv[i]; }
    __syncthreads();

    int n = blockIdx.x * blockDim.x + t;
    if (n >= nN) return;

    float rs = rsp[0];
    float nrm = fmaxf(g_agg[(size_t)nN * 40 + n], 1e-8f);
    float inv = __fdividef(1.0f, nrm);

    float a0[16], a1[24];
    {
        const float4* p0 = (const float4*)(g_agg + (size_t)n * 16);
#pragma unroll
        for (int q = 0; q < 4; q++) ((float4*)a0)[q] = p0[q];
        const float4* p1 = (const float4*)(g_agg + (size_t)nN * 16 + (size_t)n * 24);
#pragma unroll
        for (int q = 0; q < 6; q++) ((float4*)a1)[q] = p1[q];
    }
#pragma unroll
    for (int j = 0; j < 16; j++) a0[j] *= inv;
#pragma unroll
    for (int j = 0; j < 24; j++) a1[j] *= inv;

    // sc = agg0 @ Wm_s / 4
    float sc[24];
#pragma unroll
    for (int j = 0; j < 24; j++) sc[j] = 0.f;
#pragma unroll
    for (int i = 0; i < 16; i++) {
        float ai = a0[i];
#pragma unroll
        for (int j = 0; j < 24; j++) sc[j] = fmaf(ai, sWms[i * 24 + j], sc[j]);
    }

    float scal[16], gate[8];
#pragma unroll
    for (int j = 0; j < 16; j++) { float v = 0.25f * sc[j]; scal[j] = v * sigf(v); }
#pragma unroll
    for (int j = 0; j < 8;  j++) gate[j] = sigf(0.25f * sc[16 + j]);

    float vg[24];
#pragma unroll
    for (int j = 0; j < 8; j++) {
#pragma unroll
        for (int c = 0; c < 3; c++) {
            float acc = 0.f;
#pragma unroll
            for (int i = 0; i < 8; i++) acc = fmaf(a1[i * 3 + c], sWmv[i * 8 + j], acc);
            vg[3 * j + c] = acc * INV_SQRT8 * gate[j];
        }
    }

    float xs[16], xv[24];
    {
        const float4* xn = (const float4*)(g_xnorm + (size_t)n * 40);
#pragma unroll
        for (int q = 0; q < 4; q++) ((float4*)xs)[q] = xn[q];
#pragma unroll
        for (int q = 0; q < 6; q++) ((float4*)xv)[q] = xn[4 + q];
    }

    float xi[40];
    {
        const float4* xp = (const float4*)(x + (size_t)n * 40);
#pragma unroll
        for (int q = 0; q < 10; q++) ((float4*)xi)[q] = xp[q];
    }

    float ob[40];
#pragma unroll
    for (int j = 0; j < 16; j++) {
        float acc = 0.f;
#pragma unroll
        for (int i = 0; i < 16; i++) {
            acc = fmaf(scal[i], sWus[i * 16 + j], acc);
            acc = fmaf(xs[i],   sWss[i * 16 + j], acc);
        }
        ob[j] = xi[j] + rs * 0.25f * acc;
    }
#pragma unroll
    for (int j = 0; j < 8; j++) {
#pragma unroll
        for (int c = 0; c < 3; c++) {
            float acc = 0.f;
#pragma unroll
            for (int i = 0; i < 8; i++) {
                acc = fmaf(vg[3 * i + c], sWuv[i * 8 + j], acc);
                acc = fmaf(xv[3 * i + c], sWsv[i * 8 + j], acc);
            }
            ob[16 + 3 * j + c] = xi[16 + 3 * j + c] + rs * INV_SQRT8 * acc;
        }
    }

    float4* o = (float4*)(out + (size_t)n * 40);
#pragma unroll
    for (int q = 0; q < 10; q++) o[q] = ((float4*)ob)[q];
}

// ---------------------------------------------------------------------------
// Launch
// ---------------------------------------------------------------------------
extern "C" void kernel_launch(void* const* d_in, const int* in_sizes, int n_in,
                              void* d_out, int out_size)
{
    const float* x    = (const float*)d_in[0];
    const int*   esrc = (const int*)  d_in[1];
    const int*   edst = (const int*)  d_in[2];
    const float* esh  = (const float*)d_in[3];
    const float* erbf = (const float*)d_in[4];
    const float* elen = (const float*)d_in[5];
    const float* wr1  = (const float*)d_in[6];
    const float* br1  = (const float*)d_in[7];
    const float* wr2  = (const float*)d_in[8];
    const float* br2  = (const float*)d_in[9];
    const float* wg1  = (const float*)d_in[10];
    const float* bg1  = (const float*)d_in[11];
    const float* wg2  = (const float*)d_in[12];
    const float* bg2  = (const float*)d_in[13];
    const float* Wms  = (const float*)d_in[14];
    const float* Wmv  = (const float*)d_in[15];
    const float* Wus  = (const float*)d_in[16];
    const float* Wuv  = (const float*)d_in[17];
    const float* Wss  = (const float*)d_in[18];
    const float* Wsv  = (const float*)d_in[19];
    const float* rsp  = (const float*)d_in[20];

    int nN = in_sizes[0] / 40;
    int E  = in_sizes[1];
    float* out = (float*)d_out;

    size_t shbytes = 38656 * sizeof(float);   // 154624 B
    cudaFuncSetAttribute(k_edge, cudaFuncAttributeMaxDynamicSharedMemorySize, (int)shbytes);

    int totalz = nN * 41;
    k_zero<<<(totalz / 4 + 255) / 256, 256>>>(totalz);
    k_norm<<<(nN + 255) / 256, 256>>>(x, nN);
    k_edge<<<(E + 255) / 256, 256, shbytes>>>(esrc, edst, esh, erbf, elen,
                                              wr1, br1, wr2, br2,
                                              wg1, bg1, wg2, bg2, E, nN);
    k_node<<<(nN + 255) / 256, 256>>>(x, Wms, Wmv, Wus, Wuv, Wss, Wsv, rsp, out, nN);
}

// round 12
// speedup vs baseline: 3.7858x; 3.5296x over previous
#include <cuda_runtime.h>
#include <cuda_bf16.h>
#include <math.h>

typedef unsigned int u32;

// ---------------------------------------------------------------------------
// Problem constants
// ---------------------------------------------------------------------------
#define CUTOFF     5.0f
#define A_PATH     0.20412414523193150818f   // 1/sqrt(24)
#define INV_SQRT3  0.57735026918962576451f
#define INV_SQRT8  0.35355339059327376220f
#define PI_OVER_C  0.62831853071795864769f   // pi / 5

#define NNMAX 50000
__device__ float g_xnorm[NNMAX * 40];
__device__ float g_agg[NNMAX * 41];                      // agg0 | agg1 | norm
__device__ __align__(16) unsigned short g_w2bf[36864];   // W2^T bf16, [j][h] row-major

__device__ __forceinline__ float sigf(float x) {
    return __fdividef(1.0f, 1.0f + __expf(-x));
}

// m16n8k16 bf16 MMA, fp32 accumulate (baseline PTX, works on plain sm_103)
__device__ __forceinline__ void mma_bf16(float& d0, float& d1, float& d2, float& d3,
                                         u32 a0, u32 a1, u32 a2, u32 a3,
                                         u32 b0, u32 b1)
{
    asm volatile(
        "mma.sync.aligned.m16n8k16.row.col.f32.bf16.bf16.f32 "
        "{%0,%1,%2,%3}, {%4,%5,%6,%7}, {%8,%9}, {%0,%1,%2,%3};"
        : "+f"(d0), "+f"(d1), "+f"(d2), "+f"(d3)
        : "r"(a0), "r"(a1), "r"(a2), "r"(a3), "r"(b0), "r"(b1));
}

// ---------------------------------------------------------------------------
// Kernel P: W2 -> bf16 transposed  g_w2bf[j*64+h] = bf16(wr2[h*576+j])
// ---------------------------------------------------------------------------
__global__ void k_prep(const float* __restrict__ wr2)
{
    int idx = blockIdx.x * blockDim.x + threadIdx.x;
    if (idx >= 36864) return;
    int j = idx >> 6, h = idx & 63;
    g_w2bf[idx] = __bfloat16_as_ushort(__float2bfloat16_rn(wr2[h * 576 + j]));
}

// ---------------------------------------------------------------------------
// Kernel 0: zero aggregation scratch
// ---------------------------------------------------------------------------
__global__ void k_zero(int total)
{
    int i = blockIdx.x * blockDim.x + threadIdx.x;
    int nf4 = total >> 2;
    float4 z = make_float4(0.f, 0.f, 0.f, 0.f);
    if (i < nf4) ((float4*)g_agg)[i] = z;
    if (i < (total & 3)) g_agg[(nf4 << 2) + i] = 0.f;
}

// ---------------------------------------------------------------------------
// Kernel 1: irrep norm
// ---------------------------------------------------------------------------
__global__ void __launch_bounds__(256)
k_norm(const float* __restrict__ x, int nN)
{
    __shared__ float sx[256 * 40];
    int base = blockIdx.x * 256;
    int nNodes = nN - base; if (nNodes > 256) nNodes = 256;
    int nf4 = nNodes * 10;

    const float4* xin = (const float4*)(x + (size_t)base * 40);
    for (int i = threadIdx.x; i < nf4; i += 256) ((float4*)sx)[i] = xin[i];
    __syncthreads();

    int t = threadIdx.x;
    if (t < nNodes) {
        float* b = sx + t * 40;
        float ss = 0.f, vs = 0.f;
#pragma unroll
        for (int i = 0; i < 16; i++) ss = fmaf(b[i], b[i], ss);
#pragma unroll
        for (int i = 16; i < 40; i++) vs = fmaf(b[i], b[i], vs);
        float inv_s = rsqrtf(ss * 0.0625f + 1e-8f);
        float inv_v = rsqrtf(vs * 0.125f  + 1e-8f);
#pragma unroll
        for (int i = 0; i < 16; i++) b[i] *= inv_s;
#pragma unroll
        for (int i = 16; i < 40; i++) b[i] *= inv_v;
    }
    __syncthreads();
    float4* xout = (float4*)(g_xnorm + (size_t)base * 40);
    for (int i = threadIdx.x; i < nf4; i += 256) xout[i] = ((float4*)sx)[i];
}

// ---------------------------------------------------------------------------
// Kernel 2: HMMA edge kernel. CTA = 256 edges, 8 warps.
//   GEMM H[256x64] @ W2[64x576] via m16n8k16 bf16 fragments,
//   epilogue fully lane-local in fragment layout, atomic scatter.
//
// smem (u32 units):
//   sB32  [0,20736)        576 rows x 36 (32 k-pairs + pad)
//   sA32  [20736,29952)    256 rows x 36
//   sCoef [29952,+17408)   68 rows x 256 (cA24 | xs16 | pv24 | sh1x3 | ew)
//   sBr2, sWr1, sWg1, sWg2, sBr1, sBg1, sDst
// total 49408 u32 = 197632 B
// ---------------------------------------------------------------------------
__global__ void __launch_bounds__(256)
k_edge_mma(const int*   __restrict__ esrc,  const int*   __restrict__ edst,
           const float* __restrict__ esh,   const float* __restrict__ erbf,
           const float* __restrict__ elen,
           const float* __restrict__ wr1,   const float* __restrict__ br1,
           const float* __restrict__ br2g,
           const float* __restrict__ wg1,   const float* __restrict__ bg1,
           const float* __restrict__ wg2,   const float* __restrict__ bg2,
           int E, int nN)
{
    extern __shared__ __align__(16) u32 dynsm[];
    u32*   sB32  = dynsm;                     // 20736
    u32*   sA32  = dynsm + 20736;             // 9216
    float* sCoef = (float*)(dynsm + 29952);   // 17408
    float* sBr2  = sCoef + 17408;             // 576
    float* sWr1  = sBr2 + 576;                // 512
    float* sWg1  = sWr1 + 512;                // 512
    float* sWg2  = sWg1 + 512;                // 64
    float* sBr1  = sWg2 + 64;                 // 64
    float* sBg1  = sBr1 + 64;                 // 64
    int*   sDst  = (int*)(sBg1 + 64);         // 256

    const int tid  = threadIdx.x;
    const int lane = tid & 31;
    const int wid  = tid >> 5;
    const int g    = lane >> 2;
    const int tig  = lane & 3;

    // ---- stage B (bf16 W2^T) into padded rows: 4608 uint4 reads
    {
        const uint4* src = (const uint4*)g_w2bf;
        for (int i = tid; i < 4608; i += 256) {
            int j = i >> 3, q = i & 7;
            *(uint4*)(sB32 + j * 36 + q * 4) = src[i];
        }
    }
    for (int i = tid; i < 512; i += 256) { sWr1[i] = wr1[i]; sWg1[i] = wg1[i]; }
    for (int i = tid; i < 64;  i += 256) { sWg2[i] = wg2[i]; sBr1[i] = br1[i]; sBg1[i] = bg1[i]; }
    for (int i = tid; i < 576; i += 256) sBr2[i] = br2g[i];

    // ---- per-edge scalar stage
    int e = blockIdx.x * 256 + tid;
    bool valid = e < E;
    int ec = valid ? e : (E - 1);
    int src_n = esrc[ec];
    int dst_n = edst[ec];
    float4 sh4 = ((const float4*)esh)[ec];
    const float sh0 = sh4.x, s1x = sh4.y, s1y = sh4.z, s1z = sh4.w;
    float len = elen[ec];

    float rb[8];
    {
        const float4* rp = (const float4*)(erbf + (size_t)ec * 8);
        float4 r0 = rp[0], r1 = rp[1];
        rb[0] = r0.x; rb[1] = r0.y; rb[2] = r0.z; rb[3] = r0.w;
        rb[4] = r1.x; rb[5] = r1.y; rb[6] = r1.z; rb[7] = r1.w;
    }

    __syncthreads();   // weights staged before use

    float H[64], G[64];
#pragma unroll
    for (int h = 0; h < 64; h++) { H[h] = sBr1[h]; G[h] = sBg1[h]; }
#pragma unroll 1
    for (int r = 0; r < 8; r++) {
        float rv = rb[r];
        const float4* wrp = (const float4*)(sWr1 + r * 64);
        const float4* wgp = (const float4*)(sWg1 + r * 64);
#pragma unroll
        for (int h4 = 0; h4 < 16; h4++) {
            float4 wa = wrp[h4], wb = wgp[h4];
            H[4*h4+0] = fmaf(rv, wa.x, H[4*h4+0]);
            H[4*h4+1] = fmaf(rv, wa.y, H[4*h4+1]);
            H[4*h4+2] = fmaf(rv, wa.z, H[4*h4+2]);
            H[4*h4+3] = fmaf(rv, wa.w, H[4*h4+3]);
            G[4*h4+0] = fmaf(rv, wb.x, G[4*h4+0]);
            G[4*h4+1] = fmaf(rv, wb.y, G[4*h4+1]);
            G[4*h4+2] = fmaf(rv, wb.z, G[4*h4+2]);
            G[4*h4+3] = fmaf(rv, wb.w, G[4*h4+3]);
        }
    }
    float z = 0.f;
#pragma unroll
    for (int h = 0; h < 64; h++) {
        float hr = H[h]; H[h] = hr * sigf(hr);   // silu
        float hg = G[h]; z = fmaf(hg * sigf(hg), sWg2[h], z);
    }
    float gw = sigf(z + bg2[0]);
    float cw = (len < CUTOFF) ? 0.5f * (cosf(PI_OVER_C * len) + 1.0f) : 0.0f;
    float ew = (valid ? cw * gw : 0.0f);

    // ---- write A row (bf16 pairs)
    {
        u32* arow = sA32 + tid * 36;
#pragma unroll
        for (int q = 0; q < 8; q++) {
            int h = q * 8;
            u32 w0 = (u32)__bfloat16_as_ushort(__float2bfloat16_rn(H[h+0]))
                   | ((u32)__bfloat16_as_ushort(__float2bfloat16_rn(H[h+1])) << 16);
            u32 w1 = (u32)__bfloat16_as_ushort(__float2bfloat16_rn(H[h+2]))
                   | ((u32)__bfloat16_as_ushort(__float2bfloat16_rn(H[h+3])) << 16);
            u32 w2 = (u32)__bfloat16_as_ushort(__float2bfloat16_rn(H[h+4]))
                   | ((u32)__bfloat16_as_ushort(__float2bfloat16_rn(H[h+5])) << 16);
            u32 w3 = (u32)__bfloat16_as_ushort(__float2bfloat16_rn(H[h+6]))
                   | ((u32)__bfloat16_as_ushort(__float2bfloat16_rn(H[h+7])) << 16);
            *(uint4*)(arow + q * 4) = make_uint4(w0, w1, w2, w3);
        }
    }

    // ---- write per-edge coefficients (SoA, conflict-free columns)
    {
        float xe[40];
        const float4* xr = (const float4*)(g_xnorm + (size_t)src_n * 40);
#pragma unroll
        for (int q = 0; q < 10; q++) ((float4*)xe)[q] = xr[q];

#pragma unroll
        for (int i = 0; i < 16; i++) sCoef[i * 256 + tid] = xe[i] * sh0;             // cA 0..15
#pragma unroll
        for (int i = 0; i < 8; i++)                                                   // cA 16..23
            sCoef[(16 + i) * 256 + tid] =
                INV_SQRT3 * (xe[16 + 3*i] * s1x + xe[17 + 3*i] * s1y + xe[18 + 3*i] * s1z);
#pragma unroll
        for (int i = 0; i < 16; i++) sCoef[(24 + i) * 256 + tid] = xe[i];             // xs
#pragma unroll
        for (int i = 0; i < 8; i++) {                                                 // pv
            sCoef[(40 + 3*i + 0) * 256 + tid] = xe[16 + 3*i] * sh0;
            sCoef[(40 + 3*i + 1) * 256 + tid] = xe[17 + 3*i] * sh0;
            sCoef[(40 + 3*i + 2) * 256 + tid] = xe[18 + 3*i] * sh0;
        }
        sCoef[64 * 256 + tid] = s1x;
        sCoef[65 * 256 + tid] = s1y;
        sCoef[66 * 256 + tid] = s1z;
        sCoef[67 * 256 + tid] = ew;
        sDst[tid] = valid ? dst_n : 0;
    }
    __syncthreads();

    // ---- warp GEMM + fragment epilogue
    float* agg1 = g_agg + (size_t)nN * 16;
    float* nrmp = g_agg + (size_t)nN * 40;

#pragma unroll 1
    for (int rt = 0; rt < 2; rt++) {
        int rowb = wid * 32 + rt * 16;
        int e0 = rowb + g, e1 = e0 + 8;

        // A fragments for this 16-row tile (reused across all 72 col tiles)
        u32 afr[16];
        {
            const u32* a0p = sA32 + (size_t)e0 * 36;
            const u32* a1p = sA32 + (size_t)e1 * 36;
#pragma unroll
            for (int ks = 0; ks < 4; ks++) {
                afr[ks*4+0] = a0p[tig + ks*8];
                afr[ks*4+1] = a1p[tig + ks*8];
                afr[ks*4+2] = a0p[tig + 4 + ks*8];
                afr[ks*4+3] = a1p[tig + 4 + ks*8];
            }
        }

        float am0a[4] = {0,0,0,0}, am0b[4] = {0,0,0,0};
        float aU0 = 0.f, aU1 = 0.f, bU0 = 0.f, bU1 = 0.f;
        float am1a[6] = {0,0,0,0,0,0}, am1b[6] = {0,0,0,0,0,0};

#define TILE8(CT, D0, D1, D2, D3) do {                                   \
        D0 = 0.f; D1 = 0.f; D2 = 0.f; D3 = 0.f;                          \
        const u32* brow_ = sB32 + (size_t)((CT) * 8 + g) * 36;           \
        _Pragma("unroll")                                                \
        for (int ks_ = 0; ks_ < 4; ks_++) {                              \
            u32 bb0_ = brow_[tig + ks_*8];                               \
            u32 bb1_ = brow_[tig + 4 + ks_*8];                           \
            mma_bf16(D0, D1, D2, D3,                                     \
                     afr[ks_*4], afr[ks_*4+1], afr[ks_*4+2], afr[ks_*4+3], \
                     bb0_, bb1_);                                        \
        }                                                                \
    } while (0)

        // ===== m0 region: cols 0..383 (i = 0..23, tiles ct=2i, 2i+1) =====
#pragma unroll 1
        for (int i = 0; i < 24; i++) {
            float cf0 = sCoef[i * 256 + e0];
            float cf1 = sCoef[i * 256 + e1];
            {   // ct = 2i  -> local slots 0,1 (j = 2tig, 2tig+1)
                float d0, d1, d2, d3;
                TILE8(2*i, d0, d1, d2, d3);
                int J0 = i * 16 + 2 * tig;
                float2 bias = *(const float2*)(sBr2 + J0);
                am0a[0] = fmaf(cf0, d0 + bias.x, am0a[0]);
                am0a[1] = fmaf(cf0, d1 + bias.y, am0a[1]);
                am0b[0] = fmaf(cf1, d2 + bias.x, am0b[0]);
                am0b[1] = fmaf(cf1, d3 + bias.y, am0b[1]);
            }
            {   // ct = 2i+1 -> local slots 2,3 (j = 2tig+8, 2tig+9)
                float d0, d1, d2, d3;
                TILE8(2*i + 1, d0, d1, d2, d3);
                int J0 = i * 16 + 8 + 2 * tig;
                float2 bias = *(const float2*)(sBr2 + J0);
                am0a[2] = fmaf(cf0, d0 + bias.x, am0a[2]);
                am0a[3] = fmaf(cf0, d1 + bias.y, am0a[3]);
                am0b[2] = fmaf(cf1, d2 + bias.x, am0b[2]);
                am0b[3] = fmaf(cf1, d3 + bias.y, am0b[3]);
            }
        }

        // ===== w3 region: cols 384..511 (i = 0..15, ct = 48+i) =====
#pragma unroll 1
        for (int i = 0; i < 16; i++) {
            float xs0 = sCoef[(24 + i) * 256 + e0];
            float xs1 = sCoef[(24 + i) * 256 + e1];
            float d0, d1, d2, d3;
            TILE8(48 + i, d0, d1, d2, d3);
            int J0 = 384 + i * 8 + 2 * tig;
            float2 bias = *(const float2*)(sBr2 + J0);
            aU0 = fmaf(xs0, d0 + bias.x, aU0);
            aU1 = fmaf(xs0, d1 + bias.y, aU1);
            bU0 = fmaf(xs1, d2 + bias.x, bU0);
            bU1 = fmaf(xs1, d3 + bias.y, bU1);
        }

        // ===== w4 region: cols 512..575 (i = 0..7, ct = 64+i) =====
#pragma unroll 1
        for (int i = 0; i < 8; i++) {
            float p0x = sCoef[(40 + 3*i + 0) * 256 + e0];
            float p0y = sCoef[(40 + 3*i + 1) * 256 + e0];
            float p0z = sCoef[(40 + 3*i + 2) * 256 + e0];
            float p1x = sCoef[(40 + 3*i + 0) * 256 + e1];
            float p1y = sCoef[(40 + 3*i + 1) * 256 + e1];
            float p1z = sCoef[(40 + 3*i + 2) * 256 + e1];
            float d0, d1, d2, d3;
            TILE8(64 + i, d0, d1, d2, d3);
            int J0 = 512 + i * 8 + 2 * tig;
            float2 bias = *(const float2*)(sBr2 + J0);
            float t0 = d0 + bias.x, t1 = d1 + bias.y;
            float t2 = d2 + bias.x, t3 = d3 + bias.y;
            am1a[0] = fmaf(p0x, t0, am1a[0]);
            am1a[1] = fmaf(p0y, t0, am1a[1]);
            am1a[2] = fmaf(p0z, t0, am1a[2]);
            am1a[3] = fmaf(p0x, t1, am1a[3]);
            am1a[4] = fmaf(p0y, t1, am1a[4]);
            am1a[5] = fmaf(p0z, t1, am1a[5]);
            am1b[0] = fmaf(p1x, t2, am1b[0]);
            am1b[1] = fmaf(p1y, t2, am1b[1]);
            am1b[2] = fmaf(p1z, t2, am1b[2]);
            am1b[3] = fmaf(p1x, t3, am1b[3]);
            am1b[4] = fmaf(p1y, t3, am1b[4]);
            am1b[5] = fmaf(p1z, t3, am1b[5]);
        }
#undef TILE8

        // fold U (w3 path) into m1 with each edge's sh1
        {
            float sxa = sCoef[64 * 256 + e0], sya = sCoef[65 * 256 + e0], sza = sCoef[66 * 256 + e0];
            float sxb = sCoef[64 * 256 + e1], syb = sCoef[65 * 256 + e1], szb = sCoef[66 * 256 + e1];
            am1a[0] = fmaf(aU0, sxa, am1a[0]);
            am1a[1] = fmaf(aU0, sya, am1a[1]);
            am1a[2] = fmaf(aU0, sza, am1a[2]);
            am1a[3] = fmaf(aU1, sxa, am1a[3]);
            am1a[4] = fmaf(aU1, sya, am1a[4]);
            am1a[5] = fmaf(aU1, sza, am1a[5]);
            am1b[0] = fmaf(bU0, sxb, am1b[0]);
            am1b[1] = fmaf(bU0, syb, am1b[1]);
            am1b[2] = fmaf(bU0, szb, am1b[2]);
            am1b[3] = fmaf(bU1, sxb, am1b[3]);
            am1b[4] = fmaf(bU1, syb, am1b[4]);
            am1b[5] = fmaf(bU1, szb, am1b[5]);
        }

        // ---- scatter (lane-local slots)
        {
            float ew0 = sCoef[67 * 256 + e0];
            float ew1 = sCoef[67 * 256 + e1];
            int   dA  = sDst[e0];
            int   dB  = sDst[e1];
            float ca = A_PATH * ew0;
            float cb = A_PATH * ew1;
            int j0 = 2 * tig;

            float* base0 = g_agg + (size_t)dA * 16;
            atomicAdd(base0 + j0,     ca * am0a[0]);
            atomicAdd(base0 + j0 + 1, ca * am0a[1]);
            atomicAdd(base0 + j0 + 8, ca * am0a[2]);
            atomicAdd(base0 + j0 + 9, ca * am0a[3]);
            float* base1 = g_agg + (size_t)dB * 16;
            atomicAdd(base1 + j0,     cb * am0b[0]);
            atomicAdd(base1 + j0 + 1, cb * am0b[1]);
            atomicAdd(base1 + j0 + 8, cb * am0b[2]);
            atomicAdd(base1 + j0 + 9, cb * am0b[3]);

            float* v0 = agg1 + (size_t)dA * 24;
            float* v1 = agg1 + (size_t)dB * 24;
#pragma unroll
            for (int c = 0; c < 3; c++) {
                atomicAdd(v0 + 3*j0 + c,       ca * am1a[c]);
                atomicAdd(v0 + 3*(j0+1) + c,   ca * am1a[3+c]);
                atomicAdd(v1 + 3*j0 + c,       cb * am1b[c]);
                atomicAdd(v1 + 3*(j0+1) + c,   cb * am1b[3+c]);
            }
            if (tig == 0) {
                atomicAdd(nrmp + dA, ew0);
                atomicAdd(nrmp + dB, ew1);
            }
        }
    }
}

// ---------------------------------------------------------------------------
// Kernel 3: node update (gates + small matmuls + residual)
// ---------------------------------------------------------------------------
__global__ void __launch_bounds__(256)
k_node(const float* __restrict__ x,
       const float* __restrict__ Wms, const float* __restrict__ Wmv,
       const float* __restrict__ Wus, const float* __restrict__ Wuv,
       const float* __restrict__ Wss, const float* __restrict__ Wsv,
       const float* __restrict__ rsp,
       float* __restrict__ out, int nN)
{
    __shared__ float sWms[384], sWmv[64], sWus[256], sWuv[64], sWss[256], sWsv[64];
    int t = threadIdx.x;
    for (int i = t; i < 384; i += blockDim.x) sWms[i] = Wms[i];
    for (int i = t; i < 256; i += blockDim.x) { sWus[i] = Wus[i]; sWss[i] = Wss[i]; }
    for (int i = t; i < 64;  i += blockDim.x) { sWmv[i] = Wmv[i]; sWuv[i] = Wuv[i]; sWsv[i] = Wsv[i]; }
    __syncthreads();

    int n = blockIdx.x * blockDim.x + t;
    if (n >= nN) return;

    float rs = rsp[0];
    float nrm = fmaxf(g_agg[(size_t)nN * 40 + n], 1e-8f);
    float inv = __fdividef(1.0f, nrm);

    float a0[16], a1[24];
    {
        const float4* p0 = (const float4*)(g_agg + (size_t)n * 16);
#pragma unroll
        for (int q = 0; q < 4; q++) ((float4*)a0)[q] = p0[q];
        const float4* p1 = (const float4*)(g_agg + (size_t)nN * 16 + (size_t)n * 24);
#pragma unroll
        for (int q = 0; q < 6; q++) ((float4*)a1)[q] = p1[q];
    }
#pragma unroll
    for (int j = 0; j < 16; j++) a0[j] *= inv;
#pragma unroll
    for (int j = 0; j < 24; j++) a1[j] *= inv;

    float sc[24];
#pragma unroll
    for (int j = 0; j < 24; j++) sc[j] = 0.f;
#pragma unroll
    for (int i = 0; i < 16; i++) {
        float ai = a0[i];
#pragma unroll
        for (int j = 0; j < 24; j++) sc[j] = fmaf(ai, sWms[i * 24 + j], sc[j]);
    }

    float scal[16], gate[8];
#pragma unroll
    for (int j = 0; j < 16; j++) { float v = 0.25f * sc[j]; scal[j] = v * sigf(v); }
#pragma unroll
    for (int j = 0; j < 8;  j++) gate[j] = sigf(0.25f * sc[16 + j]);

    float vg[24];
#pragma unroll
    for (int j = 0; j < 8; j++) {
#pragma unroll
        for (int c = 0; c < 3; c++) {
            float acc = 0.f;
#pragma unroll
            for (int i = 0; i < 8; i++) acc = fmaf(a1[i * 3 + c], sWmv[i * 8 + j], acc);
            vg[3 * j + c] = acc * INV_SQRT8 * gate[j];
        }
    }

    float xs[16], xv[24];
    {
        const float4* xn = (const float4*)(g_xnorm + (size_t)n * 40);
#pragma unroll
        for (int q = 0; q < 4; q++) ((float4*)xs)[q] = xn[q];
#pragma unroll
        for (int q = 0; q < 6; q++) ((float4*)xv)[q] = xn[4 + q];
    }

    float xi[40];
    {
        const float4* xp = (const float4*)(x + (size_t)n * 40);
#pragma unroll
        for (int q = 0; q < 10; q++) ((float4*)xi)[q] = xp[q];
    }

    float ob[40];
#pragma unroll
    for (int j = 0; j < 16; j++) {
        float acc = 0.f;
#pragma unroll
        for (int i = 0; i < 16; i++) {
            acc = fmaf(scal[i], sWus[i * 16 + j], acc);
            acc = fmaf(xs[i],   sWss[i * 16 + j], acc);
        }
        ob[j] = xi[j] + rs * 0.25f * acc;
    }
#pragma unroll
    for (int j = 0; j < 8; j++) {
#pragma unroll
        for (int c = 0; c < 3; c++) {
            float acc = 0.f;
#pragma unroll
            for (int i = 0; i < 8; i++) {
                acc = fmaf(vg[3 * i + c], sWuv[i * 8 + j], acc);
                acc = fmaf(xv[3 * i + c], sWsv[i * 8 + j], acc);
            }
            ob[16 + 3 * j + c] = xi[16 + 3 * j + c] + rs * INV_SQRT8 * acc;
        }
    }

    float4* o = (float4*)(out + (size_t)n * 40);
#pragma unroll
    for (int q = 0; q < 10; q++) o[q] = ((float4*)ob)[q];
}

// ---------------------------------------------------------------------------
// Launch
// ---------------------------------------------------------------------------
extern "C" void kernel_launch(void* const* d_in, const int* in_sizes, int n_in,
                              void* d_out, int out_size)
{
    const float* x    = (const float*)d_in[0];
    const int*   esrc = (const int*)  d_in[1];
    const int*   edst = (const int*)  d_in[2];
    const float* esh  = (const float*)d_in[3];
    const float* erbf = (const float*)d_in[4];
    const float* elen = (const float*)d_in[5];
    const float* wr1  = (const float*)d_in[6];
    const float* br1  = (const float*)d_in[7];
    const float* wr2  = (const float*)d_in[8];
    const float* br2  = (const float*)d_in[9];
    const float* wg1  = (const float*)d_in[10];
    const float* bg1  = (const float*)d_in[11];
    const float* wg2  = (const float*)d_in[12];
    const float* bg2  = (const float*)d_in[13];
    const float* Wms  = (const float*)d_in[14];
    const float* Wmv  = (const float*)d_in[15];
    const float* Wus  = (const float*)d_in[16];
    const float* Wuv  = (const float*)d_in[17];
    const float* Wss  = (const float*)d_in[18];
    const float* Wsv  = (const float*)d_in[19];
    const float* rsp  = (const float*)d_in[20];

    int nN = in_sizes[0] / 40;
    int E  = in_sizes[1];
    float* out = (float*)d_out;

    size_t shbytes = 49408u * 4u;   // 197632 B
    cudaFuncSetAttribute(k_edge_mma, cudaFuncAttributeMaxDynamicSharedMemorySize, (int)shbytes);

    k_prep<<<(36864 + 255) / 256, 256>>>(wr2);
    int totalz = nN * 41;
    k_zero<<<(totalz / 4 + 255) / 256, 256>>>(totalz);
    k_norm<<<(nN + 255) / 256, 256>>>(x, nN);
    k_edge_mma<<<(E + 255) / 256, 256, shbytes>>>(esrc, edst, esh, erbf, elen,
                                                  wr1, br1, br2,
                                                  wg1, bg1, wg2, bg2, E, nN);
    k_node<<<(nN + 255) / 256, 256>>>(x, Wms, Wmv, Wus, Wuv, Wss, Wsv, rsp, out, nN);
}